// round 3
// baseline (speedup 1.0000x reference)
#include <cuda_runtime.h>
#include <math.h>

// Problem constants
#define B_    64
#define L_    512
#define C_    1024
#define NT    7
#define START_ 5
#define STOP_  6
#define NROWS (B_ * L_)   // 32768

__device__ float g_nll[B_];

// ---------------------------------------------------------------------------
// Kernel 1: pred = X @ W^T + b  (warp per row).
// Epilogue: write pred to d_out[1+NROWS ...], labels as float to d_out[1...].
// Register-capped (<=85) so 3 blocks/SM resident; 8 prefetched X loads/warp
// give ~24KB in flight per SM -> DRAM bandwidth-bound.
// ---------------------------------------------------------------------------
__global__ void __launch_bounds__(256, 3) k1_gemm(
    const float* __restrict__ X, const int* __restrict__ labels,
    const float* __restrict__ W, const float* __restrict__ bias,
    float* __restrict__ out)
{
    __shared__ float4 sW[NT][C_ / 4];
    __shared__ float sb[8];
    for (int i = threadIdx.x; i < NT * (C_ / 4); i += 256)
        sW[i / (C_ / 4)][i % (C_ / 4)] = ((const float4*)W)[i];
    if (threadIdx.x < NT) sb[threadIdx.x] = bias[threadIdx.x];
    __syncthreads();

    const int lane  = threadIdx.x & 31;
    const int gwarp = (blockIdx.x * blockDim.x + threadIdx.x) >> 5;
    const int nwarp = (gridDim.x * blockDim.x) >> 5;
    float* pred = out + 1 + NROWS;

    for (int row = gwarp; row < NROWS; row += nwarp) {
        const float4* xr = (const float4*)(X + (size_t)row * C_);

        // Prefetch the whole row slice for this lane (8 x 128-bit loads).
        float4 xv[8];
        #pragma unroll
        for (int k = 0; k < 8; k++) xv[k] = xr[lane + 32 * k];

        float acc[NT] = {0.f, 0.f, 0.f, 0.f, 0.f, 0.f, 0.f};
        #pragma unroll
        for (int k = 0; k < 8; k++) {
            const int idx = lane + 32 * k;
            #pragma unroll
            for (int t = 0; t < NT; t++) {
                const float4 wv = sW[t][idx];
                acc[t] = fmaf(xv[k].x, wv.x,
                          fmaf(xv[k].y, wv.y,
                           fmaf(xv[k].z, wv.z,
                            fmaf(xv[k].w, wv.w, acc[t]))));
            }
        }
        #pragma unroll
        for (int t = 0; t < NT; t++) {
            #pragma unroll
            for (int o = 16; o > 0; o >>= 1)
                acc[t] += __shfl_xor_sync(0xffffffffu, acc[t], o);
        }
        if (lane < NT) {
            pred[(size_t)row * NT + lane] = acc[lane] + sb[lane];
        } else if (lane == 8) {
            out[1 + row] = (float)labels[row];
        }
    }
}

// ---------------------------------------------------------------------------
// Kernel 2: CRF forward in exp-domain (chunked matrix products) + gold score.
// One block per batch element; 128 threads = 16 chunks x 8 columns.
// Computes exp(emissions) locally from the pred slab (L2-resident).
// ---------------------------------------------------------------------------
__global__ void __launch_bounds__(128) k2_crf(
    const float* __restrict__ trans,
    const int* __restrict__ labels,
    const float* __restrict__ outbuf)
{
    __shared__ float sEE[L_ * 8];       // 16 KB: exp-emissions for this batch
    __shared__ float sET[8][8];         // exp(transitions), padded
    __shared__ float sT[49];            // raw transitions
    __shared__ float sM[16][8][8];      // chunk matrices: [chunk][col][row]
    __shared__ float sS[16];            // chunk log-scales
    __shared__ float sv[8];
    __shared__ float sgold, svscale;

    const int b   = blockIdx.x;
    const int tid = threadIdx.x;
    const float* pred = outbuf + 1 + NROWS;

    // exp(emissions) for this batch, padded [L][8] (col 7 = 0)
    {
        const float* pb = pred + (size_t)b * L_ * NT;
        for (int i = tid; i < L_ * NT; i += 128) {
            int r = i / NT, c = i % NT;
            sEE[r * 8 + c] = expf(pb[i]);
        }
        for (int r = tid; r < L_; r += 128) sEE[r * 8 + 7] = 0.f;
    }
    if (tid < 64) {
        int n = tid >> 3, p = tid & 7;
        sET[n][p] = (n < NT && p < NT) ? expf(trans[n * NT + p]) : 0.f;
    }
    if (tid < 49) sT[tid] = trans[tid];
    __syncthreads();

    // ---- Stage A: per-chunk matrix product (thread per column) ----
    {
        const int chunk = tid >> 3;     // 0..15
        const int col   = tid & 7;      // 0..7 (7 = zero pad column)
        float ET[NT][NT];
        #pragma unroll
        for (int n = 0; n < NT; n++)
            #pragma unroll
            for (int p = 0; p < NT; p++) ET[n][p] = sET[n][p];

        const int t0 = chunk * 32;
        float u[NT];
        #pragma unroll
        for (int n = 0; n < NT; n++)
            u[n] = (col < NT) ? sET[n][col] * sEE[t0 * 8 + n] : 0.f;
        float s = 0.f;

        for (int step = 1; step < 32; step++) {
            const float* ee = &sEE[(t0 + step) * 8];
            float v[NT];
            #pragma unroll
            for (int n = 0; n < NT; n++) {
                float a = ET[n][0] * u[0];
                #pragma unroll
                for (int p = 1; p < NT; p++) a = fmaf(ET[n][p], u[p], a);
                v[n] = a * ee[n];
            }
            #pragma unroll
            for (int n = 0; n < NT; n++) u[n] = v[n];

            if ((step & 7) == 7) {      // renormalize (shared scale per chunk)
                float m = u[0];
                #pragma unroll
                for (int n = 1; n < NT; n++) m = fmaxf(m, u[n]);
                m = fmaxf(m, __shfl_xor_sync(0xffffffffu, m, 1));
                m = fmaxf(m, __shfl_xor_sync(0xffffffffu, m, 2));
                m = fmaxf(m, __shfl_xor_sync(0xffffffffu, m, 4));
                if (m > 0.f) {
                    float inv = 1.f / m;
                    #pragma unroll
                    for (int n = 0; n < NT; n++) u[n] *= inv;
                    s += logf(m);
                }
            }
        }
        #pragma unroll
        for (int n = 0; n < NT; n++) sM[chunk][col][n] = u[n];
        sM[chunk][col][7] = 0.f;
        if (col == 0) sS[chunk] = s;
    }
    __syncthreads();

    // ---- Stage B: sequential matrix-vector combine (warp 0, lanes 0..7),
    //      gold score in parallel on warp 1 ----
    if (tid < 8) {
        const int n = tid;
        float v     = sM[0][START_][n];   // init vector = e_START
        float scale = sS[0];
        for (int c = 1; c < 16; c++) {
            sv[n] = v;
            __syncwarp(0x000000ffu);
            float a = 0.f;
            #pragma unroll
            for (int j = 0; j < NT; j++) a = fmaf(sM[c][j][n], sv[j], a);
            float m = a;
            m = fmaxf(m, __shfl_xor_sync(0xffu, m, 1));
            m = fmaxf(m, __shfl_xor_sync(0xffu, m, 2));
            m = fmaxf(m, __shfl_xor_sync(0xffu, m, 4));
            if (m > 0.f) { v = a / m; scale += logf(m); }
            else         { v = a; }
            scale += sS[c];
            __syncwarp(0x000000ffu);
        }
        sv[n] = v;
        if (n == 0) svscale = scale;
    } else if (tid >= 32 && tid < 64) {
        const int lane = tid - 32;
        const int base = b * L_;
        float acc = 0.f;
        #pragma unroll 4
        for (int k = 0; k < 16; k++) {
            int t   = lane + k * 32;
            int tag = labels[base + t];
            int pt  = (t == 0) ? START_ : labels[base + t - 1];
            acc += pred[(size_t)(base + t) * NT + tag] + sT[tag * NT + pt];
        }
        #pragma unroll
        for (int o = 16; o > 0; o >>= 1)
            acc += __shfl_xor_sync(0xffffffffu, acc, o);
        if (lane == 0) sgold = acc + sT[STOP_ * NT + labels[base + L_ - 1]];
    }
    __syncthreads();

    if (tid == 0) {
        float sum = 0.f;
        #pragma unroll
        for (int n = 0; n < NT; n++) sum += sv[n] * sET[STOP_][n];
        g_nll[b] = logf(sum) + svscale - sgold;
    }
}

// ---------------------------------------------------------------------------
// Kernel 3: deterministic sum of 64 per-batch NLLs -> d_out[0]
// ---------------------------------------------------------------------------
__global__ void k3_sum(float* __restrict__ out)
{
    __shared__ float s[64];
    int t = threadIdx.x;
    s[t] = g_nll[t];
    __syncthreads();
    #pragma unroll
    for (int o = 32; o > 0; o >>= 1) {
        if (t < o) s[t] += s[t + o];
        __syncthreads();
    }
    if (t == 0) out[0] = s[0];
}

extern "C" void kernel_launch(void* const* d_in, const int* in_sizes, int n_in,
                              void* d_out, int out_size)
{
    const float* X      = (const float*)d_in[0];
    const int*   labels = (const int*)  d_in[1];
    const float* W      = (const float*)d_in[2];
    const float* bias   = (const float*)d_in[3];
    const float* trans  = (const float*)d_in[4];
    float* out = (float*)d_out;

    k1_gemm<<<1024, 256>>>(X, labels, W, bias, out);
    k2_crf<<<B_, 128>>>(trans, labels, out);
    k3_sum<<<1, 64>>>(out);
}

// round 4
// speedup vs baseline: 1.8746x; 1.8746x over previous
#include <cuda_runtime.h>
#include <math.h>

// Problem constants
#define B_    64
#define L_    512
#define C_    1024
#define NT    7
#define START_ 5
#define STOP_  6
#define NROWS (B_ * L_)   // 32768
#define NPAIRS (NROWS / 2)

__device__ float g_nll[B_];

// packed f32x2 FMA (Blackwell; PTX-only form -> single FFMA2)
__device__ __forceinline__ void ffma2(unsigned long long& d,
                                      unsigned long long a,
                                      unsigned long long b) {
    asm("fma.rn.f32x2 %0, %1, %2, %0;" : "+l"(d) : "l"(a), "l"(b));
}
// 128-bit streaming global load into two 64-bit (f32x2) regs
__device__ __forceinline__ void ldg_cs_v2b64(const void* p,
                                             unsigned long long& lo,
                                             unsigned long long& hi) {
    asm("ld.global.cs.v2.b64 {%0, %1}, [%2];" : "=l"(lo), "=l"(hi) : "l"(p));
}
__device__ __forceinline__ float unpack_sum(unsigned long long v) {
    union { unsigned long long u; float2 f; } cv; cv.u = v;
    return cv.f.x + cv.f.y;
}

// ---------------------------------------------------------------------------
// Kernel 1: pred = X @ W^T + b.  Warp per TWO rows (halves shared-W traffic),
// f32x2 packed FMAs (halves FFMA issue), 128-reg budget -> no spills,
// 16 warps/SM, persistent grid.
// ---------------------------------------------------------------------------
__global__ void __launch_bounds__(256, 2) k1_gemm(
    const float* __restrict__ X, const int* __restrict__ labels,
    const float* __restrict__ W, const float* __restrict__ bias,
    float* __restrict__ out)
{
    __shared__ unsigned long long sW[NT][C_ / 2];   // W rows as f32x2 pairs
    __shared__ float sb[8];
    for (int i = threadIdx.x; i < NT * (C_ / 2); i += 256)
        sW[i / (C_ / 2)][i % (C_ / 2)] = ((const unsigned long long*)W)[i];
    if (threadIdx.x < NT) sb[threadIdx.x] = bias[threadIdx.x];
    __syncthreads();

    const int lane  = threadIdx.x & 31;
    const int gwarp = (blockIdx.x * blockDim.x + threadIdx.x) >> 5;
    const int nwarp = (gridDim.x * blockDim.x) >> 5;
    float* pred = out + 1 + NROWS;

    for (int pair = gwarp; pair < NPAIRS; pair += nwarp) {
        const int row0 = pair * 2;
        const int row1 = row0 + 1;
        const float* x0 = X + (size_t)row0 * C_;
        const float* x1 = X + (size_t)row1 * C_;

        // Prefetch: 16 x LDG.128 (8 per row) => 8KB in flight per warp.
        unsigned long long a_lo[8], a_hi[8], b_lo[8], b_hi[8];
        #pragma unroll
        for (int k = 0; k < 8; k++) {
            const int idx = (lane + 32 * k) * 4;
            ldg_cs_v2b64(x0 + idx, a_lo[k], a_hi[k]);
            ldg_cs_v2b64(x1 + idx, b_lo[k], b_hi[k]);
        }

        unsigned long long acc0[NT], acc1[NT];
        #pragma unroll
        for (int t = 0; t < NT; t++) { acc0[t] = 0ull; acc1[t] = 0ull; }

        #pragma unroll
        for (int k = 0; k < 8; k++) {
            const int idx = (lane + 32 * k) * 2;
            #pragma unroll
            for (int t = 0; t < NT; t++) {
                const unsigned long long wlo = sW[t][idx];
                const unsigned long long whi = sW[t][idx + 1];
                ffma2(acc0[t], a_lo[k], wlo);
                ffma2(acc0[t], a_hi[k], whi);
                ffma2(acc1[t], b_lo[k], wlo);
                ffma2(acc1[t], b_hi[k], whi);
            }
        }

        float r0[NT], r1[NT];
        #pragma unroll
        for (int t = 0; t < NT; t++) {
            r0[t] = unpack_sum(acc0[t]);
            r1[t] = unpack_sum(acc1[t]);
            #pragma unroll
            for (int o = 16; o > 0; o >>= 1) {
                r0[t] += __shfl_xor_sync(0xffffffffu, r0[t], o);
                r1[t] += __shfl_xor_sync(0xffffffffu, r1[t], o);
            }
        }

        float v0 = 0.f, v1 = 0.f;
        #pragma unroll
        for (int t = 0; t < NT; t++) {
            if (lane == t)     v0 = r0[t];
            if (lane == t + 8) v1 = r1[t];
        }
        if (lane < NT) {
            pred[(size_t)row0 * NT + lane] = v0 + sb[lane];
        } else if (lane >= 8 && lane < 8 + NT) {
            pred[(size_t)row1 * NT + (lane - 8)] = v1 + sb[lane - 8];
        } else if (lane == 16) {
            out[1 + row0] = (float)labels[row0];
        } else if (lane == 17) {
            out[1 + row1] = (float)labels[row1];
        }
    }
}

// ---------------------------------------------------------------------------
// Kernel 2: CRF forward in exp-domain (chunked matrix products) + gold score.
// One block per batch element; 128 threads = 16 chunks x 8 columns.
// Computes exp(emissions) locally from the pred slab (L2-resident).
// ---------------------------------------------------------------------------
__global__ void __launch_bounds__(128) k2_crf(
    const float* __restrict__ trans,
    const int* __restrict__ labels,
    const float* __restrict__ outbuf)
{
    __shared__ float sEE[L_ * 8];       // 16 KB: exp-emissions for this batch
    __shared__ float sET[8][8];         // exp(transitions), padded
    __shared__ float sT[49];            // raw transitions
    __shared__ float sM[16][8][8];      // chunk matrices: [chunk][col][row]
    __shared__ float sS[16];            // chunk log-scales
    __shared__ float sv[8];
    __shared__ float sgold, svscale;

    const int b   = blockIdx.x;
    const int tid = threadIdx.x;
    const float* pred = outbuf + 1 + NROWS;

    {   // exp(emissions) for this batch, padded [L][8] (col 7 = 0)
        const float* pb = pred + (size_t)b * L_ * NT;
        for (int i = tid; i < L_ * NT; i += 128) {
            int r = i / NT, c = i % NT;
            sEE[r * 8 + c] = expf(pb[i]);
        }
        for (int r = tid; r < L_; r += 128) sEE[r * 8 + 7] = 0.f;
    }
    if (tid < 64) {
        int n = tid >> 3, p = tid & 7;
        sET[n][p] = (n < NT && p < NT) ? expf(trans[n * NT + p]) : 0.f;
    }
    if (tid < 49) sT[tid] = trans[tid];
    __syncthreads();

    // ---- Stage A: per-chunk matrix product (thread per column) ----
    {
        const int chunk = tid >> 3;     // 0..15
        const int col   = tid & 7;      // 0..7 (7 = zero pad column)
        float ET[NT][NT];
        #pragma unroll
        for (int n = 0; n < NT; n++)
            #pragma unroll
            for (int p = 0; p < NT; p++) ET[n][p] = sET[n][p];

        const int t0 = chunk * 32;
        float u[NT];
        #pragma unroll
        for (int n = 0; n < NT; n++)
            u[n] = (col < NT) ? sET[n][col] * sEE[t0 * 8 + n] : 0.f;
        float s = 0.f;

        for (int step = 1; step < 32; step++) {
            const float* ee = &sEE[(t0 + step) * 8];
            float v[NT];
            #pragma unroll
            for (int n = 0; n < NT; n++) {
                float a = ET[n][0] * u[0];
                #pragma unroll
                for (int p = 1; p < NT; p++) a = fmaf(ET[n][p], u[p], a);
                v[n] = a * ee[n];
            }
            #pragma unroll
            for (int n = 0; n < NT; n++) u[n] = v[n];

            if ((step & 7) == 7) {      // renormalize (shared scale per chunk)
                float m = u[0];
                #pragma unroll
                for (int n = 1; n < NT; n++) m = fmaxf(m, u[n]);
                m = fmaxf(m, __shfl_xor_sync(0xffffffffu, m, 1));
                m = fmaxf(m, __shfl_xor_sync(0xffffffffu, m, 2));
                m = fmaxf(m, __shfl_xor_sync(0xffffffffu, m, 4));
                if (m > 0.f) {
                    float inv = 1.f / m;
                    #pragma unroll
                    for (int n = 0; n < NT; n++) u[n] *= inv;
                    s += logf(m);
                }
            }
        }
        #pragma unroll
        for (int n = 0; n < NT; n++) sM[chunk][col][n] = u[n];
        sM[chunk][col][7] = 0.f;
        if (col == 0) sS[chunk] = s;
    }
    __syncthreads();

    // ---- Stage B: sequential matrix-vector combine (warp 0, lanes 0..7),
    //      gold score in parallel on warp 1 ----
    if (tid < 8) {
        const int n = tid;
        float v     = sM[0][START_][n];   // init vector = e_START
        float scale = sS[0];
        for (int c = 1; c < 16; c++) {
            sv[n] = v;
            __syncwarp(0x000000ffu);
            float a = 0.f;
            #pragma unroll
            for (int j = 0; j < NT; j++) a = fmaf(sM[c][j][n], sv[j], a);
            float m = a;
            m = fmaxf(m, __shfl_xor_sync(0xffu, m, 1));
            m = fmaxf(m, __shfl_xor_sync(0xffu, m, 2));
            m = fmaxf(m, __shfl_xor_sync(0xffu, m, 4));
            if (m > 0.f) { v = a / m; scale += logf(m); }
            else         { v = a; }
            scale += sS[c];
            __syncwarp(0x000000ffu);
        }
        sv[n] = v;
        if (n == 0) svscale = scale;
    } else if (tid >= 32 && tid < 64) {
        const int lane = tid - 32;
        const int base = b * L_;
        float acc = 0.f;
        #pragma unroll 4
        for (int k = 0; k < 16; k++) {
            int t   = lane + k * 32;
            int tag = labels[base + t];
            int pt  = (t == 0) ? START_ : labels[base + t - 1];
            acc += pred[(size_t)(base + t) * NT + tag] + sT[tag * NT + pt];
        }
        #pragma unroll
        for (int o = 16; o > 0; o >>= 1)
            acc += __shfl_xor_sync(0xffffffffu, acc, o);
        if (lane == 0) sgold = acc + sT[STOP_ * NT + labels[base + L_ - 1]];
    }
    __syncthreads();

    if (tid == 0) {
        float sum = 0.f;
        #pragma unroll
        for (int n = 0; n < NT; n++) sum += sv[n] * sET[STOP_][n];
        g_nll[b] = logf(sum) + svscale - sgold;
    }
}

// ---------------------------------------------------------------------------
// Kernel 3: deterministic sum of 64 per-batch NLLs -> d_out[0]
// ---------------------------------------------------------------------------
__global__ void k3_sum(float* __restrict__ out)
{
    __shared__ float s[64];
    int t = threadIdx.x;
    s[t] = g_nll[t];
    __syncthreads();
    #pragma unroll
    for (int o = 32; o > 0; o >>= 1) {
        if (t < o) s[t] += s[t + o];
        __syncthreads();
    }
    if (t == 0) out[0] = s[0];
}

extern "C" void kernel_launch(void* const* d_in, const int* in_sizes, int n_in,
                              void* d_out, int out_size)
{
    const float* X      = (const float*)d_in[0];
    const int*   labels = (const int*)  d_in[1];
    const float* W      = (const float*)d_in[2];
    const float* bias   = (const float*)d_in[3];
    const float* trans  = (const float*)d_in[4];
    float* out = (float*)d_out;

    k1_gemm<<<296, 256>>>(X, labels, W, bias, out);
    k2_crf<<<B_, 128>>>(trans, labels, out);
    k3_sum<<<1, 64>>>(out);
}